// round 4
// baseline (speedup 1.0000x reference)
#include <cuda_runtime.h>
#include <math.h>

#define A_ANCH 9
#define NC 80
#define CLS_C 720
#define REG_C 36
#define DPI 100
#define BATCH 4
#define CAPBIG 262144

__device__ __constant__ float c_sizes[4][3] = {
    {32.f,40.f,50.f},{64.f,80.f,101.f},{128.f,161.f,203.f},{256.f,322.f,406.f}};
__device__ __constant__ float c_ratios[3] = {0.5f,1.0f,2.0f};
__device__ __constant__ int   c_str[4] = {8,16,32,64};

#define OFF_CLS_TW 0
#define OFF_REG_TW 2359296
#define OFF_CLS_OW 4718592
#define OFF_REG_OW 6488064
#define WT_TOTAL   6782976

__device__ __align__(16) float g_b0[BATCH*256*4096];
__device__ __align__(16) float g_b1[BATCH*256*4096];
__device__ __align__(16) float g_cls[BATCH*CLS_C*5440];
__device__ __align__(16) float g_reg[BATCH*REG_C*5440];
__device__ __align__(16) float g_wt[WT_TOTAL];
__device__ unsigned g_hist[BATCH*65536];
__device__ unsigned g_thr[BATCH];
__device__ int      g_cnt[BATCH];
__device__ unsigned long long g_cand[(size_t)BATCH*CAPBIG];
__device__ unsigned long long g_sel[BATCH*4*DPI];
__device__ float g_cbox[BATCH*400*4];
__device__ float g_cscore[BATCH*400];
__device__ int   g_clab[BATCH*400];

__device__ __forceinline__ unsigned fkey(float f){
    unsigned b=__float_as_uint(f);
    return b ^ ((b>>31) ? 0xFFFFFFFFu : 0x80000000u);
}
__device__ __forceinline__ float unfkey(unsigned u){
    unsigned b=u ^ ((u>>31) ? 0x80000000u : 0xFFFFFFFFu);
    return __uint_as_float(b);
}

// ---------------- weight transform: (layer,Cout,256,3,3) -> [layer][kpos][ci][CoPad]
__global__ void wtrans_k(const float* __restrict__ src, float* __restrict__ dst,
                         int Cout, int CoPad, int nL){
    size_t total=(size_t)nL*9*256*CoPad;
    for(size_t e=(size_t)blockIdx.x*blockDim.x+threadIdx.x; e<total;
        e+=(size_t)gridDim.x*blockDim.x){
        int co=(int)(e%CoPad); size_t t=e/CoPad;
        int ci=(int)(t%256); t/=256;
        int kpos=(int)(t%9); int layer=(int)(t/9);
        float v=0.f;
        if(co<Cout) v=src[(((size_t)layer*Cout+co)*256+ci)*9+kpos];
        dst[e]=v;
    }
}

// ---------------- 3x3 SAME conv, Cin=256.  128co x 128pix block, 256 thr, 8x8 acc.
__global__ __launch_bounds__(256,2)
void conv3x3_k(const float* __restrict__ X, const float* __restrict__ Wt,
               const float* __restrict__ bias, float* __restrict__ Y,
               int H, int W, int Cout, int CoPad, int relu){
    const int HW=H*W;
    const int b=blockIdx.z;
    const int coBase=blockIdx.y<<7;
    const int pixBase=blockIdx.x<<7;
    const int tid=threadIdx.x;
    const int tx=tid&15, ty=tid>>4;
    __shared__ float Ws[8][128];
    __shared__ float Xs[8][132];
    float acc[8][8];
#pragma unroll
    for(int i=0;i<8;i++)
#pragma unroll
        for(int j=0;j<8;j++) acc[i][j]=0.f;
    const int li=tid>>5;
    const int lp0=(tid&31)<<2;
    int lh[4],lw[4]; bool lq[4];
#pragma unroll
    for(int d=0;d<4;d++){
        int q=pixBase+lp0+d; lq[d]=q<HW; int qq=lq[d]?q:0;
        lh[d]=qq/W; lw[d]=qq-lh[d]*W;
    }
    const float* Xb=X+(size_t)b*256*HW;
    const int lco=(tid&31)<<2;
    for(int kpos=0;kpos<9;kpos++){
        const int kh=kpos/3-1, kw=kpos-(kpos/3)*3-1;
        int xoff[4]; bool xv[4];
#pragma unroll
        for(int d=0;d<4;d++){
            int hh=lh[d]+kh, ww=lw[d]+kw;
            xv[d]=lq[d]&&hh>=0&&hh<H&&ww>=0&&ww<W;
            xoff[d]=hh*W+ww;
        }
        const float* wbase=Wt+(size_t)kpos*256*CoPad+coBase+lco;
        for(int c0=0;c0<256;c0+=8){
            float4 wv=*(const float4*)(wbase+(size_t)(c0+li)*CoPad);
            *(float4*)&Ws[li][lco]=wv;
            const float* xrow=Xb+(size_t)(c0+li)*HW;
#pragma unroll
            for(int d=0;d<4;d++) Xs[li][lp0+d]=xv[d]?xrow[xoff[d]]:0.f;
            __syncthreads();
#pragma unroll
            for(int k=0;k<8;k++){
                float a[8],bb[8];
                *(float4*)&a[0]=*(const float4*)&Ws[k][ty<<3];
                *(float4*)&a[4]=*(const float4*)&Ws[k][(ty<<3)+4];
                *(float4*)&bb[0]=*(const float4*)&Xs[k][tx<<3];
                *(float4*)&bb[4]=*(const float4*)&Xs[k][(tx<<3)+4];
#pragma unroll
                for(int i=0;i<8;i++)
#pragma unroll
                    for(int j=0;j<8;j++) acc[i][j]+=a[i]*bb[j];
            }
            __syncthreads();
        }
    }
#pragma unroll
    for(int i=0;i<8;i++){
        int co=coBase+(ty<<3)+i;
        if(co<Cout){
            float bv=bias[co];
            float* yrow=Y+((size_t)b*Cout+co)*HW;
#pragma unroll
            for(int j=0;j<8;j++){
                int pix=pixBase+(tx<<3)+j;
                if(pix<HW){
                    float v=acc[i][j]+bv;
                    if(relu) v=fmaxf(v,0.f);
                    yrow[pix]=v;
                }
            }
        }
    }
}

// fp32 sigmoid, matching 1/(1+exp(-x)) rounding
__device__ __forceinline__ float sigm(float v){
    return 1.0f/(1.0f+expf(-v));
}
// candidacy: sigmoid(v) > 0.05 in fp32
__device__ __forceinline__ bool is_cand(float v){
    if(v>-2.93f) return true;
    if(v<=-2.96f) return false;
    return sigm(v)>0.05f;
}

__global__ void zero_k(){
    int i=blockIdx.x*blockDim.x+threadIdx.x;
    if(i<BATCH*65536) g_hist[i]=0;
    if(i<BATCH) g_cnt[i]=0;
}

// histogram over SCORE key hi-16 (equal scores share a bin -> ties collected whole)
__global__ void hist_k(const float* __restrict__ base, int n){
    int b=blockIdx.y;
    const float* p=base+(size_t)b*n;
    for(int m=blockIdx.x*blockDim.x+threadIdx.x;m<n;m+=gridDim.x*blockDim.x){
        float v=p[m];
        if(is_cand(v)){
            unsigned u=fkey(sigm(v));
            atomicAdd(&g_hist[b*65536+(u>>16)],1u);
        }
    }
}

__global__ void scan_k(){
    int b=blockIdx.x;
    __shared__ unsigned seg[256];
    const unsigned* h=&g_hist[b*65536];
    unsigned s=0; int base=threadIdx.x*256;
    for(int k=0;k<256;k++) s+=h[65535-(base+k)];
    seg[threadIdx.x]=s;
    __syncthreads();
    if(threadIdx.x==0){
        unsigned cum=0,thr=0;
        for(int sg=0;sg<256;sg++){
            if(cum+seg[sg]>=DPI){
                for(int k=0;k<256;k++){
                    cum+=h[65535-(sg*256+k)];
                    if(cum>=DPI){thr=65535-(sg*256+k);break;}
                }
                break;
            }
            cum+=seg[sg];
        }
        g_thr[b]=thr;
    }
}

// collect all candidates in score-bins >= thr, key = scorebits || ~flatindex
__global__ void collect_k(const float* __restrict__ base, int n, int HW){
    int b=blockIdx.y;
    unsigned thr=g_thr[b];
    const float* p=base+(size_t)b*n;
    for(int m=blockIdx.x*blockDim.x+threadIdx.x;m<n;m+=gridDim.x*blockDim.x){
        float v=p[m];
        if(!is_cand(v)) continue;
        unsigned u=fkey(sigm(v));
        if((u>>16)>=thr){
            int pos=atomicAdd(&g_cnt[b],1);
            if(pos<CAPBIG){
                int co=m/HW, pix=m-co*HW;
                unsigned nn=(unsigned)(pix*CLS_C+co);
                g_cand[(size_t)b*CAPBIG+pos]=((unsigned long long)u<<32)|(0xFFFFFFFFu-nn);
            }
        }
    }
}

// exact top-100 by (score desc, index asc): 100 x argmax (robust to huge tie classes)
__global__ __launch_bounds__(1024)
void select_k(int lvl){
    int b=blockIdx.x;
    int cnt=g_cnt[b]; if(cnt>CAPBIG) cnt=CAPBIG;
    __shared__ unsigned long long sk[1024];
    __shared__ int sp[1024];
    unsigned long long* cand=&g_cand[(size_t)b*CAPBIG];
    for(int r=0;r<DPI;r++){
        unsigned long long mk=0ULL; int mp=-1;
        for(int i=threadIdx.x;i<cnt;i+=1024){
            unsigned long long k=cand[i];
            if(k>mk){mk=k;mp=i;}
        }
        sk[threadIdx.x]=mk; sp[threadIdx.x]=mp;
        __syncthreads();
        for(int s=512;s>0;s>>=1){
            if(threadIdx.x<s){
                if(sk[threadIdx.x+s]>sk[threadIdx.x]){
                    sk[threadIdx.x]=sk[threadIdx.x+s];
                    sp[threadIdx.x]=sp[threadIdx.x+s];
                }
            }
            __syncthreads();
        }
        if(threadIdx.x==0){
            g_sel[(b*4+lvl)*DPI+r]=sk[0];
            if(sp[0]>=0) cand[sp[0]]=0ULL;
        }
        __syncthreads();
    }
}

__global__ void decode_k(int lvl,int H,int W,const float* __restrict__ Rlvl,
                         const int* __restrict__ ph,const int* __restrict__ pw){
    int b=blockIdx.x, r=threadIdx.x;
    if(r>=DPI) return;
    int HW=H*W;
    float ih=(float)(*ph), iw=(float)(*pw);
    int slot=b*400+lvl*DPI+r;
    unsigned long long k=g_sel[(b*4+lvl)*DPI+r];
    float* bx=&g_cbox[(size_t)slot*4];
    if(!k){ g_cscore[slot]=-1.f; g_clab[slot]=-1; bx[0]=bx[1]=bx[2]=bx[3]=0.f; return; }
    float sc=unfkey((unsigned)(k>>32));
    unsigned n=0xFFFFFFFFu-(unsigned)(k&0xFFFFFFFFu);
    int pix=(int)(n/CLS_C); int co=(int)(n-(unsigned)pix*CLS_C);
    int a=co/NC, c=co-a*NC;
    int hh=pix/W, ww=pix-hh*W;
    float size=c_sizes[lvl][a%3];
    float hr=sqrtf(c_ratios[a/3]);
    float wr=1.f/hr;
    float ws=wr*size, hs=hr*size;
    float st=(float)c_str[lvl];
    float sx=(float)ww*st, sy=(float)hh*st;
    float ax1=fminf(fmaxf(sx+rintf(-ws*0.5f),0.f),iw);
    float ay1=fminf(fmaxf(sy+rintf(-hs*0.5f),0.f),ih);
    float ax2=fminf(fmaxf(sx+rintf( ws*0.5f),0.f),iw);
    float ay2=fminf(fmaxf(sy+rintf( hs*0.5f),0.f),ih);
    float aw=ax2-ax1, ah=ay2-ay1;
    float cx=ax1+0.5f*aw, cy=ay1+0.5f*ah;
    const float* R=Rlvl+(size_t)b*REG_C*HW;
    float dx=R[(a*4+0)*HW+pix];
    float dy=R[(a*4+1)*HW+pix];
    const float CLIPV=(float)4.135166556742356;
    float dw=fminf(R[(a*4+2)*HW+pix],CLIPV);
    float dh=fminf(R[(a*4+3)*HW+pix],CLIPV);
    float pcx=dx*aw+cx, pcy=dy*ah+cy;
    float pw_=expf(dw)*aw, ph_=expf(dh)*ah;
    bx[0]=fminf(fmaxf(pcx-0.5f*pw_,0.f),iw);
    bx[1]=fminf(fmaxf(pcy-0.5f*ph_,0.f),ih);
    bx[2]=fminf(fmaxf(pcx+0.5f*pw_,0.f),iw);
    bx[3]=fminf(fmaxf(pcy+0.5f*ph_,0.f),ih);
    g_cscore[slot]=sc;
    g_clab[slot]=c;
}

__global__ __launch_bounds__(512)
void final_k(float* __restrict__ out,const int* __restrict__ ph,const int* __restrict__ pw){
    int b=blockIdx.x, tid=threadIdx.x;
    __shared__ unsigned long long key[512];
    __shared__ float X1[512],Y1[512],X2[512],Y2[512],AR[512],SC[512];
    __shared__ float BX1[512],BY1[512],BX2[512],BY2[512];
    __shared__ int LB[512];
    __shared__ unsigned char KP[512];
    float ih=(float)(*ph), iw=(float)(*pw);
    float ob=fmaxf(ih,iw)+1.f;
    if(tid<400)
        key[tid]=((unsigned long long)fkey(g_cscore[b*400+tid])<<32)|(0xFFFFFFFFu-(unsigned)tid);
    else key[tid]=0ULL;
    __syncthreads();
    for(int k=2;k<=512;k<<=1)
        for(int j=k>>1;j>0;j>>=1){
            int ix=tid^j;
            if(ix>tid){
                unsigned long long a=key[tid],c=key[ix];
                if((a>c)==((tid&k)==0)){key[tid]=c;key[ix]=a;}
            }
            __syncthreads();
        }
    {
        unsigned long long k=key[511-tid];
        float sc=-1.f; int lb=-1; float b0=0,b1=0,b2=0,b3=0;
        if(k){
            unsigned i=0xFFFFFFFFu-(unsigned)(k&0xFFFFFFFFu);
            sc=unfkey((unsigned)(k>>32));
            lb=g_clab[b*400+i];
            const float* bp=&g_cbox[((size_t)b*400+i)*4];
            b0=bp[0];b1=bp[1];b2=bp[2];b3=bp[3];
        }
        float o=(float)lb*ob;
        BX1[tid]=b0;BY1[tid]=b1;BX2[tid]=b2;BY2[tid]=b3;
        X1[tid]=b0+o;Y1[tid]=b1+o;X2[tid]=b2+o;Y2[tid]=b3+o;
        SC[tid]=sc;LB[tid]=lb;
        AR[tid]=(X2[tid]-X1[tid])*(Y2[tid]-Y1[tid]);
        KP[tid]=(sc>0.05f)?1:0;
    }
    __syncthreads();
    for(int i=0;i<400;i++){
        if(KP[i]&&tid>i&&tid<400&&KP[tid]){
            float w=fmaxf(fminf(X2[i],X2[tid])-fmaxf(X1[i],X1[tid]),0.f);
            float h=fmaxf(fminf(Y2[i],Y2[tid])-fmaxf(Y1[i],Y1[tid]),0.f);
            float it=w*h;
            float iou=it/(AR[i]+AR[tid]-it+1e-9f);
            if(iou>0.5f) KP[tid]=0;
        }
        __syncthreads();
    }
    if(tid==0){
        int o=0;
        for(int r=0;r<400&&o<DPI;r++) if(KP[r]){
            out[(b*DPI+o)*4+0]=BX1[r]; out[(b*DPI+o)*4+1]=BY1[r];
            out[(b*DPI+o)*4+2]=BX2[r]; out[(b*DPI+o)*4+3]=BY2[r];
            out[1600+b*DPI+o]=SC[r];   out[2000+b*DPI+o]=(float)LB[r];
            o++;
        }
        for(;o<DPI;o++){
            out[(b*DPI+o)*4+0]=0.f; out[(b*DPI+o)*4+1]=0.f;
            out[(b*DPI+o)*4+2]=0.f; out[(b*DPI+o)*4+3]=0.f;
            out[1600+b*DPI+o]=0.f;  out[2000+b*DPI+o]=-1.f;
        }
    }
}

extern "C" void kernel_launch(void* const* d_in, const int* in_sizes, int n_in,
                              void* d_out, int out_size){
    const float* f[4]={(const float*)d_in[0],(const float*)d_in[1],
                       (const float*)d_in[2],(const float*)d_in[3]};
    const float* ctw=(const float*)d_in[4];
    const float* ctb=(const float*)d_in[5];
    const float* cow=(const float*)d_in[6];
    const float* cob=(const float*)d_in[7];
    const float* rtw=(const float*)d_in[8];
    const float* rtb=(const float*)d_in[9];
    const float* row_=(const float*)d_in[10];
    const float* rob=(const float*)d_in[11];
    const int* ph=(const int*)d_in[12];
    const int* pw=(const int*)d_in[13];

    float *b0,*b1,*cls,*reg,*wt;
    cudaGetSymbolAddress((void**)&b0,g_b0);
    cudaGetSymbolAddress((void**)&b1,g_b1);
    cudaGetSymbolAddress((void**)&cls,g_cls);
    cudaGetSymbolAddress((void**)&reg,g_reg);
    cudaGetSymbolAddress((void**)&wt,g_wt);

    wtrans_k<<<2048,256>>>(ctw,wt+OFF_CLS_TW,256,256,4);
    wtrans_k<<<2048,256>>>(rtw,wt+OFF_REG_TW,256,256,4);
    wtrans_k<<<2048,256>>>(cow,wt+OFF_CLS_OW,720,768,1);
    wtrans_k<<<1024,256>>>(row_,wt+OFF_REG_OW,36,128,1);

    static const int LH[4]={64,32,16,8}, LW[4]={64,32,16,8};
    static const int cum[5]={0,4096,5120,5376,5440};

    for(int lvl=0;lvl<4;lvl++){
        int H=LH[lvl],W=LW[lvl],HW=H*W;
        dim3 gT((HW+127)/128,2,BATCH);
        conv3x3_k<<<gT,256>>>(f[lvl],wt+OFF_CLS_TW+0*589824,ctb+0,  b0,H,W,256,256,1);
        conv3x3_k<<<gT,256>>>(b0,    wt+OFF_CLS_TW+1*589824,ctb+256,b1,H,W,256,256,1);
        conv3x3_k<<<gT,256>>>(b1,    wt+OFF_CLS_TW+2*589824,ctb+512,b0,H,W,256,256,1);
        conv3x3_k<<<gT,256>>>(b0,    wt+OFF_CLS_TW+3*589824,ctb+768,b1,H,W,256,256,1);
        dim3 gC((HW+127)/128,6,BATCH);
        float* clsL=cls+(size_t)CLS_C*BATCH*cum[lvl];
        conv3x3_k<<<gC,256>>>(b1,wt+OFF_CLS_OW,cob,clsL,H,W,720,768,0);
        conv3x3_k<<<gT,256>>>(f[lvl],wt+OFF_REG_TW+0*589824,rtb+0,  b0,H,W,256,256,1);
        conv3x3_k<<<gT,256>>>(b0,    wt+OFF_REG_TW+1*589824,rtb+256,b1,H,W,256,256,1);
        conv3x3_k<<<gT,256>>>(b1,    wt+OFF_REG_TW+2*589824,rtb+512,b0,H,W,256,256,1);
        conv3x3_k<<<gT,256>>>(b0,    wt+OFF_REG_TW+3*589824,rtb+768,b1,H,W,256,256,1);
        dim3 gR((HW+127)/128,1,BATCH);
        float* regL=reg+(size_t)REG_C*BATCH*cum[lvl];
        conv3x3_k<<<gR,256>>>(b1,wt+OFF_REG_OW,rob,regL,H,W,36,128,0);

        int n=CLS_C*HW;
        int nb=(n+255)/256; if(nb>2048) nb=2048;
        zero_k<<<(BATCH*65536+255)/256,256>>>();
        hist_k<<<dim3(nb,BATCH),256>>>(clsL,n);
        scan_k<<<BATCH,256>>>();
        collect_k<<<dim3(nb,BATCH),256>>>(clsL,n,HW);
        select_k<<<BATCH,1024>>>(lvl);
        decode_k<<<BATCH,128>>>(lvl,H,W,regL,ph,pw);
    }
    final_k<<<BATCH,512>>>((float*)d_out,ph,pw);
}

// round 5
// speedup vs baseline: 1.0028x; 1.0028x over previous
#include <cuda_runtime.h>
#include <math.h>

#define A_ANCH 9
#define NC 80
#define CLS_C 720
#define REG_C 36
#define DPI 100
#define BATCH 4
#define CAPBIG 262144

__device__ __constant__ float c_sizes[4][3] = {
    {32.f,40.f,50.f},{64.f,80.f,101.f},{128.f,161.f,203.f},{256.f,322.f,406.f}};
__device__ __constant__ float c_ratios[3] = {0.5f,1.0f,2.0f};
__device__ __constant__ int   c_str[4] = {8,16,32,64};

#define OFF_CLS_TW 0
#define OFF_REG_TW 2359296
#define OFF_CLS_OW 4718592
#define OFF_REG_OW 6488064
#define WT_TOTAL   6782976

__device__ __align__(16) float g_b0[BATCH*256*4096];
__device__ __align__(16) float g_b1[BATCH*256*4096];
__device__ __align__(16) float g_cls[BATCH*CLS_C*5440];
__device__ __align__(16) float g_reg[BATCH*REG_C*5440];
__device__ __align__(16) float g_wt[WT_TOTAL];
__device__ unsigned g_hist[BATCH*65536];
__device__ unsigned g_thr[BATCH];
__device__ int      g_cnt[BATCH];
__device__ unsigned long long g_cand[(size_t)BATCH*CAPBIG];
__device__ unsigned long long g_sel[BATCH*4*DPI];
__device__ float g_cbox[BATCH*400*4];
__device__ float g_cscore[BATCH*400];
__device__ int   g_clab[BATCH*400];

__device__ __forceinline__ unsigned fkey(float f){
    unsigned b=__float_as_uint(f);
    return b ^ ((b>>31) ? 0xFFFFFFFFu : 0x80000000u);
}
__device__ __forceinline__ float unfkey(unsigned u){
    unsigned b=u ^ ((u>>31) ? 0x80000000u : 0xFFFFFFFFu);
    return __uint_as_float(b);
}

// ---------------- weight transform: (layer,Cout,256,3,3) -> [layer][kpos][ci][CoPad]
__global__ void wtrans_k(const float* __restrict__ src, float* __restrict__ dst,
                         int Cout, int CoPad, int nL){
    size_t total=(size_t)nL*9*256*CoPad;
    for(size_t e=(size_t)blockIdx.x*blockDim.x+threadIdx.x; e<total;
        e+=(size_t)gridDim.x*blockDim.x){
        int co=(int)(e%CoPad); size_t t=e/CoPad;
        int ci=(int)(t%256); t/=256;
        int kpos=(int)(t%9); int layer=(int)(t/9);
        float v=0.f;
        if(co<Cout) v=src[(((size_t)layer*Cout+co)*256+ci)*9+kpos];
        dst[e]=v;
    }
}

// ---------------- 3x3 SAME conv, Cin=256.  128co x 128pix block, 256 thr, 8x8 acc.
__global__ __launch_bounds__(256,2)
void conv3x3_k(const float* __restrict__ X, const float* __restrict__ Wt,
               const float* __restrict__ bias, float* __restrict__ Y,
               int H, int W, int Cout, int CoPad, int relu){
    const int HW=H*W;
    const int b=blockIdx.z;
    const int coBase=blockIdx.y<<7;
    const int pixBase=blockIdx.x<<7;
    const int tid=threadIdx.x;
    const int tx=tid&15, ty=tid>>4;
    __shared__ float Ws[8][128];
    __shared__ float Xs[8][132];
    float acc[8][8];
#pragma unroll
    for(int i=0;i<8;i++)
#pragma unroll
        for(int j=0;j<8;j++) acc[i][j]=0.f;
    const int li=tid>>5;
    const int lp0=(tid&31)<<2;
    int lh[4],lw[4]; bool lq[4];
#pragma unroll
    for(int d=0;d<4;d++){
        int q=pixBase+lp0+d; lq[d]=q<HW; int qq=lq[d]?q:0;
        lh[d]=qq/W; lw[d]=qq-lh[d]*W;
    }
    const float* Xb=X+(size_t)b*256*HW;
    const int lco=(tid&31)<<2;
    for(int kpos=0;kpos<9;kpos++){
        const int kh=kpos/3-1, kw=kpos-(kpos/3)*3-1;
        int xoff[4]; bool xv[4];
#pragma unroll
        for(int d=0;d<4;d++){
            int hh=lh[d]+kh, ww=lw[d]+kw;
            xv[d]=lq[d]&&hh>=0&&hh<H&&ww>=0&&ww<W;
            xoff[d]=hh*W+ww;
        }
        const float* wbase=Wt+(size_t)kpos*256*CoPad+coBase+lco;
        for(int c0=0;c0<256;c0+=8){
            float4 wv=*(const float4*)(wbase+(size_t)(c0+li)*CoPad);
            *(float4*)&Ws[li][lco]=wv;
            const float* xrow=Xb+(size_t)(c0+li)*HW;
#pragma unroll
            for(int d=0;d<4;d++) Xs[li][lp0+d]=xv[d]?xrow[xoff[d]]:0.f;
            __syncthreads();
#pragma unroll
            for(int k=0;k<8;k++){
                float a[8],bb[8];
                *(float4*)&a[0]=*(const float4*)&Ws[k][ty<<3];
                *(float4*)&a[4]=*(const float4*)&Ws[k][(ty<<3)+4];
                *(float4*)&bb[0]=*(const float4*)&Xs[k][tx<<3];
                *(float4*)&bb[4]=*(const float4*)&Xs[k][(tx<<3)+4];
#pragma unroll
                for(int i=0;i<8;i++)
#pragma unroll
                    for(int j=0;j<8;j++) acc[i][j]+=a[i]*bb[j];
            }
            __syncthreads();
        }
    }
#pragma unroll
    for(int i=0;i<8;i++){
        int co=coBase+(ty<<3)+i;
        if(co<Cout){
            float bv=bias[co];
            float* yrow=Y+((size_t)b*Cout+co)*HW;
#pragma unroll
            for(int j=0;j<8;j++){
                int pix=pixBase+(tx<<3)+j;
                if(pix<HW){
                    float v=acc[i][j]+bv;
                    if(relu) v=fmaxf(v,0.f);
                    yrow[pix]=v;
                }
            }
        }
    }
}

// fp32 sigmoid, matching 1/(1+exp(-x)) rounding
__device__ __forceinline__ float sigm(float v){
    return 1.0f/(1.0f+expf(-v));
}
// candidacy: sigmoid(v) > 0.05 in fp32
__device__ __forceinline__ bool is_cand(float v){
    if(v>-2.93f) return true;
    if(v<=-2.96f) return false;
    return sigm(v)>0.05f;
}

__global__ void zero_k(){
    int i=blockIdx.x*blockDim.x+threadIdx.x;
    if(i<BATCH*65536) g_hist[i]=0;
    if(i<BATCH) g_cnt[i]=0;
}

// histogram over SCORE key hi-16 (equal scores share a bin -> ties collected whole)
__global__ void hist_k(const float* __restrict__ base, int n){
    int b=blockIdx.y;
    const float* p=base+(size_t)b*n;
    for(int m=blockIdx.x*blockDim.x+threadIdx.x;m<n;m+=gridDim.x*blockDim.x){
        float v=p[m];
        if(is_cand(v)){
            unsigned u=fkey(sigm(v));
            atomicAdd(&g_hist[b*65536+(u>>16)],1u);
        }
    }
}

__global__ void scan_k(){
    int b=blockIdx.x;
    __shared__ unsigned seg[256];
    const unsigned* h=&g_hist[b*65536];
    unsigned s=0; int base=threadIdx.x*256;
    for(int k=0;k<256;k++) s+=h[65535-(base+k)];
    seg[threadIdx.x]=s;
    __syncthreads();
    if(threadIdx.x==0){
        unsigned cum=0,thr=0;
        for(int sg=0;sg<256;sg++){
            if(cum+seg[sg]>=DPI){
                for(int k=0;k<256;k++){
                    cum+=h[65535-(sg*256+k)];
                    if(cum>=DPI){thr=65535-(sg*256+k);break;}
                }
                break;
            }
            cum+=seg[sg];
        }
        g_thr[b]=thr;
    }
}

// collect all candidates in score-bins >= thr, key = scorebits || ~flatindex
__global__ void collect_k(const float* __restrict__ base, int n, int HW){
    int b=blockIdx.y;
    unsigned thr=g_thr[b];
    const float* p=base+(size_t)b*n;
    for(int m=blockIdx.x*blockDim.x+threadIdx.x;m<n;m+=gridDim.x*blockDim.x){
        float v=p[m];
        if(!is_cand(v)) continue;
        unsigned u=fkey(sigm(v));
        if((u>>16)>=thr){
            int pos=atomicAdd(&g_cnt[b],1);
            if(pos<CAPBIG){
                int co=m/HW, pix=m-co*HW;
                unsigned nn=(unsigned)(pix*CLS_C+co);
                g_cand[(size_t)b*CAPBIG+pos]=((unsigned long long)u<<32)|(0xFFFFFFFFu-nn);
            }
        }
    }
}

// exact top-100 by (score desc, index asc): 100 x argmax (robust to huge tie classes)
__global__ __launch_bounds__(1024)
void select_k(int lvl){
    int b=blockIdx.x;
    int cnt=g_cnt[b]; if(cnt>CAPBIG) cnt=CAPBIG;
    __shared__ unsigned long long sk[1024];
    __shared__ int sp[1024];
    unsigned long long* cand=&g_cand[(size_t)b*CAPBIG];
    for(int r=0;r<DPI;r++){
        unsigned long long mk=0ULL; int mp=-1;
        for(int i=threadIdx.x;i<cnt;i+=1024){
            unsigned long long k=cand[i];
            if(k>mk){mk=k;mp=i;}
        }
        sk[threadIdx.x]=mk; sp[threadIdx.x]=mp;
        __syncthreads();
        for(int s=512;s>0;s>>=1){
            if(threadIdx.x<s){
                if(sk[threadIdx.x+s]>sk[threadIdx.x]){
                    sk[threadIdx.x]=sk[threadIdx.x+s];
                    sp[threadIdx.x]=sp[threadIdx.x+s];
                }
            }
            __syncthreads();
        }
        if(threadIdx.x==0){
            g_sel[(b*4+lvl)*DPI+r]=sk[0];
            if(sp[0]>=0) cand[sp[0]]=0ULL;
        }
        __syncthreads();
    }
}

__global__ void decode_k(int lvl,int H,int W,const float* __restrict__ Rlvl,
                         const int* __restrict__ ph,const int* __restrict__ pw){
    int b=blockIdx.x, r=threadIdx.x;
    if(r>=DPI) return;
    int HW=H*W;
    float ih=(float)(*ph), iw=(float)(*pw);
    int slot=b*400+lvl*DPI+r;
    unsigned long long k=g_sel[(b*4+lvl)*DPI+r];
    float* bx=&g_cbox[(size_t)slot*4];
    if(!k){ g_cscore[slot]=-1.f; g_clab[slot]=-1; bx[0]=bx[1]=bx[2]=bx[3]=0.f; return; }
    float sc=unfkey((unsigned)(k>>32));
    unsigned n=0xFFFFFFFFu-(unsigned)(k&0xFFFFFFFFu);
    int pix=(int)(n/CLS_C); int co=(int)(n-(unsigned)pix*CLS_C);
    int a=co/NC, c=co-a*NC;
    int hh=pix/W, ww=pix-hh*W;
    float size=c_sizes[lvl][a%3];
    float hr=sqrtf(c_ratios[a/3]);
    float wr=1.f/hr;
    float ws=wr*size, hs=hr*size;
    float st=(float)c_str[lvl];
    float sx=(float)ww*st, sy=(float)hh*st;
    float ax1=fminf(fmaxf(sx+rintf(-ws*0.5f),0.f),iw);
    float ay1=fminf(fmaxf(sy+rintf(-hs*0.5f),0.f),ih);
    float ax2=fminf(fmaxf(sx+rintf( ws*0.5f),0.f),iw);
    float ay2=fminf(fmaxf(sy+rintf( hs*0.5f),0.f),ih);
    float aw=ax2-ax1, ah=ay2-ay1;
    float cx=ax1+0.5f*aw, cy=ay1+0.5f*ah;
    const float* R=Rlvl+(size_t)b*REG_C*HW;
    float dx=R[(a*4+0)*HW+pix];
    float dy=R[(a*4+1)*HW+pix];
    const float CLIPV=(float)4.135166556742356;
    float dw=fminf(R[(a*4+2)*HW+pix],CLIPV);
    float dh=fminf(R[(a*4+3)*HW+pix],CLIPV);
    float pcx=dx*aw+cx, pcy=dy*ah+cy;
    float pw_=expf(dw)*aw, ph_=expf(dh)*ah;
    bx[0]=fminf(fmaxf(pcx-0.5f*pw_,0.f),iw);
    bx[1]=fminf(fmaxf(pcy-0.5f*ph_,0.f),ih);
    bx[2]=fminf(fmaxf(pcx+0.5f*pw_,0.f),iw);
    bx[3]=fminf(fmaxf(pcy+0.5f*ph_,0.f),ih);
    g_cscore[slot]=sc;
    g_clab[slot]=c;
}

__global__ __launch_bounds__(512)
void final_k(float* __restrict__ out,const int* __restrict__ ph,const int* __restrict__ pw){
    int b=blockIdx.x, tid=threadIdx.x;
    __shared__ unsigned long long key[512];
    __shared__ float X1[512],Y1[512],X2[512],Y2[512],AR[512],SC[512];
    __shared__ float BX1[512],BY1[512],BX2[512],BY2[512];
    __shared__ int LB[512];
    __shared__ unsigned char KP[512];
    float ih=(float)(*ph), iw=(float)(*pw);
    float ob=fmaxf(ih,iw)+1.f;
    if(tid<400)
        key[tid]=((unsigned long long)fkey(g_cscore[b*400+tid])<<32)|(0xFFFFFFFFu-(unsigned)tid);
    else key[tid]=0ULL;
    __syncthreads();
    for(int k=2;k<=512;k<<=1)
        for(int j=k>>1;j>0;j>>=1){
            int ix=tid^j;
            if(ix>tid){
                unsigned long long a=key[tid],c=key[ix];
                if((a>c)==((tid&k)==0)){key[tid]=c;key[ix]=a;}
            }
            __syncthreads();
        }
    {
        unsigned long long k=key[511-tid];
        float sc=-1.f; int lb=-1; float b0=0,b1=0,b2=0,b3=0;
        if(k){
            unsigned i=0xFFFFFFFFu-(unsigned)(k&0xFFFFFFFFu);
            sc=unfkey((unsigned)(k>>32));
            lb=g_clab[b*400+i];
            const float* bp=&g_cbox[((size_t)b*400+i)*4];
            b0=bp[0];b1=bp[1];b2=bp[2];b3=bp[3];
        }
        float o=(float)lb*ob;
        BX1[tid]=b0;BY1[tid]=b1;BX2[tid]=b2;BY2[tid]=b3;
        X1[tid]=b0+o;Y1[tid]=b1+o;X2[tid]=b2+o;Y2[tid]=b3+o;
        SC[tid]=sc;LB[tid]=lb;
        AR[tid]=(X2[tid]-X1[tid])*(Y2[tid]-Y1[tid]);
        KP[tid]=(sc>0.05f)?1:0;
    }
    __syncthreads();
    for(int i=0;i<400;i++){
        if(KP[i]&&tid>i&&tid<400&&KP[tid]){
            float w=fmaxf(fminf(X2[i],X2[tid])-fmaxf(X1[i],X1[tid]),0.f);
            float h=fmaxf(fminf(Y2[i],Y2[tid])-fmaxf(Y1[i],Y1[tid]),0.f);
            float it=w*h;
            float iou=it/(AR[i]+AR[tid]-it+1e-9f);
            if(iou>0.5f) KP[tid]=0;
        }
        __syncthreads();
    }
    if(tid==0){
        int o=0;
        for(int r=0;r<400&&o<DPI;r++) if(KP[r]){
            out[(b*DPI+o)*4+0]=BX1[r]; out[(b*DPI+o)*4+1]=BY1[r];
            out[(b*DPI+o)*4+2]=BX2[r]; out[(b*DPI+o)*4+3]=BY2[r];
            out[1600+b*DPI+o]=SC[r];   out[2000+b*DPI+o]=(float)LB[r];
            o++;
        }
        for(;o<DPI;o++){
            out[(b*DPI+o)*4+0]=0.f; out[(b*DPI+o)*4+1]=0.f;
            out[(b*DPI+o)*4+2]=0.f; out[(b*DPI+o)*4+3]=0.f;
            out[1600+b*DPI+o]=0.f;  out[2000+b*DPI+o]=-1.f;
        }
    }
}

extern "C" void kernel_launch(void* const* d_in, const int* in_sizes, int n_in,
                              void* d_out, int out_size){
    const float* f[4]={(const float*)d_in[0],(const float*)d_in[1],
                       (const float*)d_in[2],(const float*)d_in[3]};
    const float* ctw=(const float*)d_in[4];
    const float* ctb=(const float*)d_in[5];
    const float* cow=(const float*)d_in[6];
    const float* cob=(const float*)d_in[7];
    const float* rtw=(const float*)d_in[8];
    const float* rtb=(const float*)d_in[9];
    const float* row_=(const float*)d_in[10];
    const float* rob=(const float*)d_in[11];
    const int* ph=(const int*)d_in[12];
    const int* pw=(const int*)d_in[13];

    float *b0,*b1,*cls,*reg,*wt;
    cudaGetSymbolAddress((void**)&b0,g_b0);
    cudaGetSymbolAddress((void**)&b1,g_b1);
    cudaGetSymbolAddress((void**)&cls,g_cls);
    cudaGetSymbolAddress((void**)&reg,g_reg);
    cudaGetSymbolAddress((void**)&wt,g_wt);

    wtrans_k<<<2048,256>>>(ctw,wt+OFF_CLS_TW,256,256,4);
    wtrans_k<<<2048,256>>>(rtw,wt+OFF_REG_TW,256,256,4);
    wtrans_k<<<2048,256>>>(cow,wt+OFF_CLS_OW,720,768,1);
    wtrans_k<<<1024,256>>>(row_,wt+OFF_REG_OW,36,128,1);

    static const int LH[4]={64,32,16,8}, LW[4]={64,32,16,8};
    static const int cum[5]={0,4096,5120,5376,5440};

    for(int lvl=0;lvl<4;lvl++){
        int H=LH[lvl],W=LW[lvl],HW=H*W;
        dim3 gT((HW+127)/128,2,BATCH);
        conv3x3_k<<<gT,256>>>(f[lvl],wt+OFF_CLS_TW+0*589824,ctb+0,  b0,H,W,256,256,1);
        conv3x3_k<<<gT,256>>>(b0,    wt+OFF_CLS_TW+1*589824,ctb+256,b1,H,W,256,256,1);
        conv3x3_k<<<gT,256>>>(b1,    wt+OFF_CLS_TW+2*589824,ctb+512,b0,H,W,256,256,1);
        conv3x3_k<<<gT,256>>>(b0,    wt+OFF_CLS_TW+3*589824,ctb+768,b1,H,W,256,256,1);
        dim3 gC((HW+127)/128,6,BATCH);
        float* clsL=cls+(size_t)CLS_C*BATCH*cum[lvl];
        conv3x3_k<<<gC,256>>>(b1,wt+OFF_CLS_OW,cob,clsL,H,W,720,768,0);
        conv3x3_k<<<gT,256>>>(f[lvl],wt+OFF_REG_TW+0*589824,rtb+0,  b0,H,W,256,256,1);
        conv3x3_k<<<gT,256>>>(b0,    wt+OFF_REG_TW+1*589824,rtb+256,b1,H,W,256,256,1);
        conv3x3_k<<<gT,256>>>(b1,    wt+OFF_REG_TW+2*589824,rtb+512,b0,H,W,256,256,1);
        conv3x3_k<<<gT,256>>>(b0,    wt+OFF_REG_TW+3*589824,rtb+768,b1,H,W,256,256,1);
        dim3 gR((HW+127)/128,1,BATCH);
        float* regL=reg+(size_t)REG_C*BATCH*cum[lvl];
        conv3x3_k<<<gR,256>>>(b1,wt+OFF_REG_OW,rob,regL,H,W,36,128,0);

        int n=CLS_C*HW;
        int nb=(n+255)/256; if(nb>2048) nb=2048;
        zero_k<<<(BATCH*65536+255)/256,256>>>();
        hist_k<<<dim3(nb,BATCH),256>>>(clsL,n);
        scan_k<<<BATCH,256>>>();
        collect_k<<<dim3(nb,BATCH),256>>>(clsL,n,HW);
        select_k<<<BATCH,1024>>>(lvl);
        decode_k<<<BATCH,128>>>(lvl,H,W,regL,ph,pw);
    }
    final_k<<<BATCH,512>>>((float*)d_out,ph,pw);
}

// round 6
// speedup vs baseline: 2.0301x; 2.0243x over previous
#include <cuda_runtime.h>
#include <math.h>

#define NC 80
#define CLS_C 720
#define REG_C 36
#define DPI 100
#define BATCH 4
#define CAPB 131072

// -------- level tables --------
__constant__ int cb_W[4]   = {64,32,16,8};
__constant__ int cb_HW[4]  = {4096,1024,256,64};
__constant__ int cb_LW[4]  = {6,5,4,3};
__constant__ int cb_CUM[4] = {0,4096,5120,5376};
// 43 pixel-blocks: 32 (lvl0) + 8 (lvl1) + 2 (lvl2) + 1 (lvl3)
__constant__ int cb_lvl[43] = {0,0,0,0,0,0,0,0,0,0,0,0,0,0,0,0,
                               0,0,0,0,0,0,0,0,0,0,0,0,0,0,0,0,
                               1,1,1,1,1,1,1,1, 2,2, 3};
__constant__ int cb_pix[43] = {0,128,256,384,512,640,768,896,1024,1152,1280,1408,
                               1536,1664,1792,1920,2048,2176,2304,2432,2560,2688,
                               2816,2944,3072,3200,3328,3456,3584,3712,3840,3968,
                               0,128,256,384,512,640,768,896, 0,128, 0};

__device__ __constant__ float c_sizes[4][3] = {
    {32.f,40.f,50.f},{64.f,80.f,101.f},{128.f,161.f,203.f},{256.f,322.f,406.f}};
__device__ __constant__ float c_ratios[3] = {0.5f,1.0f,2.0f};
__device__ __constant__ int   c_str[4] = {8,16,32,64};

#define OFF_CLS_TW 0
#define OFF_REG_TW 2359296
#define OFF_CLS_OW 4718592
#define OFF_REG_OW 6488064

// -------- scratch --------
__device__ __align__(16) float g_b0[2*BATCH*256*5440];
__device__ __align__(16) float g_b1[2*BATCH*256*5440];
__device__ __align__(16) float g_cls[BATCH*CLS_C*5440];
__device__ __align__(16) float g_reg[BATCH*REG_C*5440];
__device__ __align__(16) float g_wt[6782976];
__device__ unsigned g_hist[16*65536];
__device__ unsigned g_thr[16];
__device__ int      g_cnt[16];
__device__ unsigned long long g_cand[(size_t)16*CAPB];
__device__ unsigned long long g_sel[16*DPI];
__device__ float g_cbox[BATCH*400*4];
__device__ float g_cscore[BATCH*400];
__device__ int   g_clab[BATCH*400];

__device__ __forceinline__ unsigned fkey(float f){
    unsigned b=__float_as_uint(f);
    return b ^ ((b>>31) ? 0xFFFFFFFFu : 0x80000000u);
}
__device__ __forceinline__ float unfkey(unsigned u){
    unsigned b=u ^ ((u>>31) ? 0x80000000u : 0xFFFFFFFFu);
    return __uint_as_float(b);
}

// -------- weight transform: (layer,Cout,256,3,3) -> [layer][kpos][ci][CoPad]
__global__ void wtrans_k(const float* __restrict__ src, float* __restrict__ dst,
                         int Cout, int CoPad, int nL){
    size_t total=(size_t)nL*9*256*CoPad;
    for(size_t e=(size_t)blockIdx.x*blockDim.x+threadIdx.x; e<total;
        e+=(size_t)gridDim.x*blockDim.x){
        int co=(int)(e%CoPad); size_t t=e/CoPad;
        int ci=(int)(t%256); t/=256;
        int kpos=(int)(t%9); int layer=(int)(t/9);
        float v=0.f;
        if(co<Cout) v=src[(((size_t)layer*Cout+co)*256+ci)*9+kpos];
        dst[e]=v;
    }
}

// -------- conv core: 3x3 SAME, Cin=256, halo-tiled X (staged once per ci-block)
__device__ __forceinline__ void conv_core(
    const float* __restrict__ Xb, int xStride,
    const float* __restrict__ Wt, int CoPad, int Cout,
    const float* __restrict__ bias,
    float* __restrict__ Yb, int yStride,
    int W, int H, int HW, int lw, int pixBase, int coBase, int relu,
    float* Ws, float* Xs){
    const int tid=threadIdx.x;
    const int tx=tid&15, ty=tid>>4;
    int validPx = HW - pixBase; if(validPx>128) validPx=128;
    const int SRS = W+4;
    const int hR = (validPx>>lw)+2;
    const int ES = hR*SRS;
    const int pixRow0 = pixBase>>lw;

    int goff0=0,goff1=0; bool v0=false,v1=false;
    const int e0=tid, e1=tid+256;
    if(e0<ES){int hr=e0/SRS;int c=e0-hr*SRS;int gr=pixRow0-1+hr;int gc=c-1;
        v0=(gr>=0&&gr<H&&gc>=0&&gc<W); goff0=gr*W+gc;}
    if(e1<ES){int hr=e1/SRS;int c=e1-hr*SRS;int gr=pixRow0-1+hr;int gc=c-1;
        v1=(gr>=0&&gr<H&&gc>=0&&gc<W); goff1=gr*W+gc;}

    const int px0=tx<<3;
    const bool pvalid = px0<validPx;
    const int prow = pvalid ? (px0>>lw) : 0;
    const int pcol = px0&(W-1);

    float acc[8][8];
#pragma unroll
    for(int i=0;i<8;i++)
#pragma unroll
        for(int j=0;j<8;j++) acc[i][j]=0.f;

    for(int c0=0;c0<256;c0+=8){
#pragma unroll
        for(int i=0;i<9;i++){
            int q=tid*4+i*1024;
            int kpos=q>>10, ciL=(q>>7)&7, co=q&127;
            *(float4*)&Ws[q] =
                *(const float4*)&Wt[((size_t)(kpos*256+c0+ciL))*CoPad + coBase+co];
        }
#pragma unroll
        for(int ciL=0;ciL<8;ciL++){
            const float* xr=Xb+(size_t)(c0+ciL)*xStride;
            if(e0<ES) Xs[ciL*272+e0]= v0? xr[goff0]:0.f;
            if(e1<ES) Xs[ciL*272+e1]= v1? xr[goff1]:0.f;
        }
        __syncthreads();
#pragma unroll
        for(int k=0;k<8;k++){
            const int xbse=k*272;
#pragma unroll
            for(int kh=0;kh<3;kh++){
                const int rb=xbse+(prow+kh)*SRS+pcol;
                float xr[10];
                float4 u=*(const float4*)&Xs[rb];
                float4 v=*(const float4*)&Xs[rb+4];
                xr[0]=u.x;xr[1]=u.y;xr[2]=u.z;xr[3]=u.w;
                xr[4]=v.x;xr[5]=v.y;xr[6]=v.z;xr[7]=v.w;
                xr[8]=Xs[rb+8]; xr[9]=Xs[rb+9];
#pragma unroll
                for(int kw=0;kw<3;kw++){
                    const float* wrow=&Ws[((kh*3+kw)*8+k)*128+(ty<<3)];
                    float4 a0=*(const float4*)wrow;
                    float4 a1=*(const float4*)(wrow+4);
                    float a[8];
                    a[0]=a0.x;a[1]=a0.y;a[2]=a0.z;a[3]=a0.w;
                    a[4]=a1.x;a[5]=a1.y;a[6]=a1.z;a[7]=a1.w;
#pragma unroll
                    for(int i=0;i<8;i++)
#pragma unroll
                        for(int j=0;j<8;j++)
                            acc[i][j] += a[i]*xr[kw+j];
                }
            }
        }
        __syncthreads();
    }
    if(pvalid){
#pragma unroll
        for(int i=0;i<8;i++){
            int co=coBase+(ty<<3)+i;
            if(co<Cout){
                float bv=bias[co];
                float* yr=Yb+(size_t)co*yStride + pixBase+px0;
#pragma unroll
                for(int j=0;j<8;j++){
                    float vv=acc[i][j]+bv;
                    if(relu) vv=fmaxf(vv,0.f);
                    yr[j]=vv;
                }
            }
        }
    }
}

// -------- tower layer: all levels + both towers fused
__global__ __launch_bounds__(256,2)
void conv_tower_k(const float* __restrict__ xin,
                  const float* __restrict__ f0,const float* __restrict__ f1,
                  const float* __restrict__ f2,const float* __restrict__ f3,
                  const float* __restrict__ wtC,const float* __restrict__ wtR,
                  const float* __restrict__ bC,const float* __restrict__ bR,
                  float* __restrict__ out,int first){
    __shared__ float Ws[9216];
    __shared__ float Xs[8*272];
    const int bx=blockIdx.x;
    const int lvl=cb_lvl[bx], pixBase=cb_pix[bx];
    const int tower=blockIdx.y>>1, coBase=(blockIdx.y&1)<<7;
    const int b=blockIdx.z;
    const int W=cb_W[lvl],HW=cb_HW[lvl],lw=cb_LW[lvl],cum=cb_CUM[lvl];
    const float* Xb; int xs;
    if(first){
        const float* fl = (lvl==0)?f0:(lvl==1)?f1:(lvl==2)?f2:f3;
        Xb = fl + (size_t)b*256*HW; xs=HW;
    }else{
        Xb = xin + ((size_t)(tower*4+b)*256)*5440 + cum; xs=5440;
    }
    float* Yb = out + ((size_t)(tower*4+b)*256)*5440 + cum;
    conv_core(Xb,xs, tower?wtR:wtC, 256,256, tower?bR:bC,
              Yb,5440, W,W,HW,lw,pixBase,coBase,1, Ws,Xs);
}

// -------- heads: y<6 cls (720ch), y==6 reg (36ch)
__global__ __launch_bounds__(256,2)
void conv_head_k(const float* __restrict__ xin,
                 const float* __restrict__ wtCO,const float* __restrict__ wtRO,
                 const float* __restrict__ cob,const float* __restrict__ rob,
                 float* __restrict__ clsOut,float* __restrict__ regOut){
    __shared__ float Ws[9216];
    __shared__ float Xs[8*272];
    const int bx=blockIdx.x;
    const int lvl=cb_lvl[bx], pixBase=cb_pix[bx];
    const int y=blockIdx.y, b=blockIdx.z;
    const int W=cb_W[lvl],HW=cb_HW[lvl],lw=cb_LW[lvl],cum=cb_CUM[lvl];
    if(y<6){
        const float* Xb = xin + ((size_t)b*256)*5440 + cum;
        float* Yb = clsOut + (size_t)CLS_C*4*cum + (size_t)b*CLS_C*HW;
        conv_core(Xb,5440, wtCO,768,720, cob, Yb,HW,
                  W,W,HW,lw,pixBase,y*128,0, Ws,Xs);
    }else{
        const float* Xb = xin + ((size_t)(4+b)*256)*5440 + cum;
        float* Yb = regOut + (size_t)REG_C*4*cum + (size_t)b*REG_C*HW;
        conv_core(Xb,5440, wtRO,128,36, rob, Yb,HW,
                  W,W,HW,lw,pixBase,0,0, Ws,Xs);
    }
}

// -------- selection --------
__device__ __forceinline__ float sigm(float v){ return 1.0f/(1.0f+expf(-v)); }
__device__ __forceinline__ bool is_cand(float v){
    if(v>-2.93f) return true;
    if(v<=-2.96f) return false;
    return sigm(v)>0.05f;
}

__global__ void zero_k(){
    int i=blockIdx.x*blockDim.x+threadIdx.x;
    if(i<16*65536) g_hist[i]=0;
    if(i<16) g_cnt[i]=0;
}

__global__ void hist_k(const float* __restrict__ cls){
    const int g=blockIdx.y, b=g>>2, lvl=g&3;
    const int HW=cb_HW[lvl], n=CLS_C*HW;
    const float* p=cls + (size_t)CLS_C*4*cb_CUM[lvl] + (size_t)b*n;
    for(int m=blockIdx.x*blockDim.x+threadIdx.x;m<n;m+=gridDim.x*blockDim.x){
        float v=p[m];
        if(is_cand(v)) atomicAdd(&g_hist[g*65536+(fkey(sigm(v))>>16)],1u);
    }
}

__global__ void scan_k(){
    const int g=blockIdx.x;
    __shared__ unsigned seg[256];
    const unsigned* h=&g_hist[g*65536];
    unsigned s=0; int base=threadIdx.x*256;
    for(int k=0;k<256;k++) s+=h[65535-(base+k)];
    seg[threadIdx.x]=s;
    __syncthreads();
    if(threadIdx.x==0){
        unsigned cum=0,thr=0;
        for(int sg=0;sg<256;sg++){
            if(cum+seg[sg]>=DPI){
                for(int k=0;k<256;k++){
                    cum+=h[65535-(sg*256+k)];
                    if(cum>=DPI){thr=65535-(sg*256+k);break;}
                }
                break;
            }
            cum+=seg[sg];
        }
        g_thr[g]=thr;
    }
}

__global__ void collect_k(const float* __restrict__ cls){
    const int g=blockIdx.y, b=g>>2, lvl=g&3;
    const int HW=cb_HW[lvl], n=CLS_C*HW;
    const unsigned thr=g_thr[g];
    const float* p=cls + (size_t)CLS_C*4*cb_CUM[lvl] + (size_t)b*n;
    for(int m=blockIdx.x*blockDim.x+threadIdx.x;m<n;m+=gridDim.x*blockDim.x){
        float v=p[m];
        if(!is_cand(v)) continue;
        unsigned u=fkey(sigm(v));
        if((u>>16)>=thr){
            int pos=atomicAdd(&g_cnt[g],1);
            if(pos<CAPB){
                int co=m/HW, pix=m-co*HW;
                unsigned nn=(unsigned)(pix*CLS_C+co);
                g_cand[(size_t)g*CAPB+pos]=((unsigned long long)u<<32)|(0xFFFFFFFFu-nn);
            }
        }
    }
}

// exact top-100 by (score desc, index asc): 100 x argmax with smem cache
__global__ __launch_bounds__(256)
void select_k(){
    const int g=blockIdx.x;
    int cnt=g_cnt[g]; if(cnt>CAPB) cnt=CAPB;
    unsigned long long* cand=&g_cand[(size_t)g*CAPB];
    __shared__ unsigned long long sc[4096];
    __shared__ unsigned long long wmax[8];
    __shared__ int wpos[8];
    const int tid=threadIdx.x, lane=tid&31, wid=tid>>5;
    const bool cached = cnt<=4096;
    if(cached) for(int i=tid;i<cnt;i+=256) sc[i]=cand[i];
    __syncthreads();
    unsigned long long* src = cached? sc : cand;
    for(int r=0;r<DPI;r++){
        unsigned long long mk=0ULL; int mp=-1;
        for(int i=tid;i<cnt;i+=256){
            unsigned long long k=src[i];
            if(k>mk){mk=k;mp=i;}
        }
#pragma unroll
        for(int off=16;off>0;off>>=1){
            unsigned long long ok=__shfl_down_sync(0xFFFFFFFFu,mk,off);
            int op=__shfl_down_sync(0xFFFFFFFFu,mp,off);
            if(ok>mk){mk=ok;mp=op;}
        }
        if(lane==0){wmax[wid]=mk;wpos[wid]=mp;}
        __syncthreads();
        if(tid==0){
            unsigned long long bk=wmax[0]; int bp=wpos[0];
#pragma unroll
            for(int w=1;w<8;w++) if(wmax[w]>bk){bk=wmax[w];bp=wpos[w];}
            g_sel[g*DPI+r]=bk;
            if(bp>=0) src[bp]=0ULL;
        }
        __syncthreads();
    }
}

__global__ void decode_k(const float* __restrict__ reg,
                         const int* __restrict__ ph,const int* __restrict__ pw){
    const int g=blockIdx.x, b=g>>2, lvl=g&3;
    const int r=threadIdx.x;
    if(r>=DPI) return;
    const int W=cb_W[lvl], HW=cb_HW[lvl];
    const float ih=(float)(*ph), iw=(float)(*pw);
    const int slot=b*400+lvl*DPI+r;
    unsigned long long k=g_sel[g*DPI+r];
    float* bx=&g_cbox[(size_t)slot*4];
    if(!k){ g_cscore[slot]=-1.f; g_clab[slot]=-1; bx[0]=bx[1]=bx[2]=bx[3]=0.f; return; }
    float sc=unfkey((unsigned)(k>>32));
    unsigned n=0xFFFFFFFFu-(unsigned)(k&0xFFFFFFFFu);
    int pix=(int)(n/CLS_C); int co=(int)(n-(unsigned)pix*CLS_C);
    int a=co/NC, c=co-a*NC;
    int hh=pix/W, ww=pix-hh*W;
    float size=c_sizes[lvl][a%3];
    float hr=sqrtf(c_ratios[a/3]);
    float wr=1.f/hr;
    float ws=wr*size, hs=hr*size;
    float st=(float)c_str[lvl];
    float sx=(float)ww*st, sy=(float)hh*st;
    float ax1=fminf(fmaxf(sx+rintf(-ws*0.5f),0.f),iw);
    float ay1=fminf(fmaxf(sy+rintf(-hs*0.5f),0.f),ih);
    float ax2=fminf(fmaxf(sx+rintf( ws*0.5f),0.f),iw);
    float ay2=fminf(fmaxf(sy+rintf( hs*0.5f),0.f),ih);
    float aw=ax2-ax1, ah=ay2-ay1;
    float cx=ax1+0.5f*aw, cy=ay1+0.5f*ah;
    const float* R=reg + (size_t)REG_C*4*cb_CUM[lvl] + (size_t)b*REG_C*HW;
    float dx=R[(a*4+0)*HW+pix];
    float dy=R[(a*4+1)*HW+pix];
    const float CLIPV=(float)4.135166556742356;
    float dw=fminf(R[(a*4+2)*HW+pix],CLIPV);
    float dh=fminf(R[(a*4+3)*HW+pix],CLIPV);
    float pcx=dx*aw+cx, pcy=dy*ah+cy;
    float pw_=expf(dw)*aw, ph_=expf(dh)*ah;
    bx[0]=fminf(fmaxf(pcx-0.5f*pw_,0.f),iw);
    bx[1]=fminf(fmaxf(pcy-0.5f*ph_,0.f),ih);
    bx[2]=fminf(fmaxf(pcx+0.5f*pw_,0.f),iw);
    bx[3]=fminf(fmaxf(pcy+0.5f*ph_,0.f),ih);
    g_cscore[slot]=sc;
    g_clab[slot]=c;
}

__global__ __launch_bounds__(512)
void final_k(float* __restrict__ out,const int* __restrict__ ph,const int* __restrict__ pw){
    int b=blockIdx.x, tid=threadIdx.x;
    __shared__ unsigned long long key[512];
    __shared__ float X1[512],Y1[512],X2[512],Y2[512],AR[512],SC[512];
    __shared__ float BX1[512],BY1[512],BX2[512],BY2[512];
    __shared__ int LB[512];
    __shared__ unsigned char KP[512];
    float ih=(float)(*ph), iw=(float)(*pw);
    float ob=fmaxf(ih,iw)+1.f;
    if(tid<400)
        key[tid]=((unsigned long long)fkey(g_cscore[b*400+tid])<<32)|(0xFFFFFFFFu-(unsigned)tid);
    else key[tid]=0ULL;
    __syncthreads();
    for(int k=2;k<=512;k<<=1)
        for(int j=k>>1;j>0;j>>=1){
            int ix=tid^j;
            if(ix>tid){
                unsigned long long a=key[tid],c=key[ix];
                if((a>c)==((tid&k)==0)){key[tid]=c;key[ix]=a;}
            }
            __syncthreads();
        }
    {
        unsigned long long k=key[511-tid];
        float sc=-1.f; int lb=-1; float b0=0,b1=0,b2=0,b3=0;
        if(k){
            unsigned i=0xFFFFFFFFu-(unsigned)(k&0xFFFFFFFFu);
            sc=unfkey((unsigned)(k>>32));
            lb=g_clab[b*400+i];
            const float* bp=&g_cbox[((size_t)b*400+i)*4];
            b0=bp[0];b1=bp[1];b2=bp[2];b3=bp[3];
        }
        float o=(float)lb*ob;
        BX1[tid]=b0;BY1[tid]=b1;BX2[tid]=b2;BY2[tid]=b3;
        X1[tid]=b0+o;Y1[tid]=b1+o;X2[tid]=b2+o;Y2[tid]=b3+o;
        SC[tid]=sc;LB[tid]=lb;
        AR[tid]=(X2[tid]-X1[tid])*(Y2[tid]-Y1[tid]);
        KP[tid]=(sc>0.05f)?1:0;
    }
    __syncthreads();
    for(int i=0;i<400;i++){
        if(KP[i]&&tid>i&&tid<400&&KP[tid]){
            float w=fmaxf(fminf(X2[i],X2[tid])-fmaxf(X1[i],X1[tid]),0.f);
            float h=fmaxf(fminf(Y2[i],Y2[tid])-fmaxf(Y1[i],Y1[tid]),0.f);
            float it=w*h;
            float iou=it/(AR[i]+AR[tid]-it+1e-9f);
            if(iou>0.5f) KP[tid]=0;
        }
        __syncthreads();
    }
    if(tid==0){
        int o=0;
        for(int r=0;r<400&&o<DPI;r++) if(KP[r]){
            out[(b*DPI+o)*4+0]=BX1[r]; out[(b*DPI+o)*4+1]=BY1[r];
            out[(b*DPI+o)*4+2]=BX2[r]; out[(b*DPI+o)*4+3]=BY2[r];
            out[1600+b*DPI+o]=SC[r];   out[2000+b*DPI+o]=(float)LB[r];
            o++;
        }
        for(;o<DPI;o++){
            out[(b*DPI+o)*4+0]=0.f; out[(b*DPI+o)*4+1]=0.f;
            out[(b*DPI+o)*4+2]=0.f; out[(b*DPI+o)*4+3]=0.f;
            out[1600+b*DPI+o]=0.f;  out[2000+b*DPI+o]=-1.f;
        }
    }
}

extern "C" void kernel_launch(void* const* d_in, const int* in_sizes, int n_in,
                              void* d_out, int out_size){
    const float* f0=(const float*)d_in[0];
    const float* f1=(const float*)d_in[1];
    const float* f2=(const float*)d_in[2];
    const float* f3=(const float*)d_in[3];
    const float* ctw=(const float*)d_in[4];
    const float* ctb=(const float*)d_in[5];
    const float* cow=(const float*)d_in[6];
    const float* cob=(const float*)d_in[7];
    const float* rtw=(const float*)d_in[8];
    const float* rtb=(const float*)d_in[9];
    const float* row_=(const float*)d_in[10];
    const float* rob=(const float*)d_in[11];
    const int* ph=(const int*)d_in[12];
    const int* pw=(const int*)d_in[13];

    float *b0,*b1,*cls,*reg,*wt;
    cudaGetSymbolAddress((void**)&b0,g_b0);
    cudaGetSymbolAddress((void**)&b1,g_b1);
    cudaGetSymbolAddress((void**)&cls,g_cls);
    cudaGetSymbolAddress((void**)&reg,g_reg);
    cudaGetSymbolAddress((void**)&wt,g_wt);

    wtrans_k<<<2048,256>>>(ctw,wt+OFF_CLS_TW,256,256,4);
    wtrans_k<<<2048,256>>>(rtw,wt+OFF_REG_TW,256,256,4);
    wtrans_k<<<2048,256>>>(cow,wt+OFF_CLS_OW,720,768,1);
    wtrans_k<<<1024,256>>>(row_,wt+OFF_REG_OW,36,128,1);

    const float* wtC=wt+OFF_CLS_TW;
    const float* wtR=wt+OFF_REG_TW;

    // 4 tower layers (both towers, all levels, all images fused per launch)
    conv_tower_k<<<dim3(43,4,BATCH),256>>>(b1,f0,f1,f2,f3,
        wtC+0*589824,wtR+0*589824,ctb+0,  rtb+0,  b0,1);
    conv_tower_k<<<dim3(43,4,BATCH),256>>>(b0,f0,f1,f2,f3,
        wtC+1*589824,wtR+1*589824,ctb+256,rtb+256,b1,0);
    conv_tower_k<<<dim3(43,4,BATCH),256>>>(b1,f0,f1,f2,f3,
        wtC+2*589824,wtR+2*589824,ctb+512,rtb+512,b0,0);
    conv_tower_k<<<dim3(43,4,BATCH),256>>>(b0,f0,f1,f2,f3,
        wtC+3*589824,wtR+3*589824,ctb+768,rtb+768,b1,0);
    // heads
    conv_head_k<<<dim3(43,7,BATCH),256>>>(b1,wt+OFF_CLS_OW,wt+OFF_REG_OW,
        cob,rob,cls,reg);

    // selection (all 16 (b,lvl) pairs concurrent)
    zero_k<<<4096,256>>>();
    hist_k<<<dim3(256,16),256>>>(cls);
    scan_k<<<16,256>>>();
    collect_k<<<dim3(256,16),256>>>(cls);
    select_k<<<16,256>>>();
    decode_k<<<16,128>>>(reg,ph,pw);
    final_k<<<BATCH,512>>>((float*)d_out,ph,pw);
}

// round 7
// speedup vs baseline: 2.6747x; 1.3176x over previous
#include <cuda_runtime.h>
#include <math.h>

#define NC 80
#define CLS_C 720
#define REG_C 36
#define DPI 100
#define BATCH 4
#define CAPB 131072

// -------- level tables --------
__constant__ int cb_W[4]   = {64,32,16,8};
__constant__ int cb_HW[4]  = {4096,1024,256,64};
__constant__ int cb_LW[4]  = {6,5,4,3};
__constant__ int cb_CUM[4] = {0,4096,5120,5376};
__constant__ int cb_lvl[43] = {0,0,0,0,0,0,0,0,0,0,0,0,0,0,0,0,
                               0,0,0,0,0,0,0,0,0,0,0,0,0,0,0,0,
                               1,1,1,1,1,1,1,1, 2,2, 3};
__constant__ int cb_pix[43] = {0,128,256,384,512,640,768,896,1024,1152,1280,1408,
                               1536,1664,1792,1920,2048,2176,2304,2432,2560,2688,
                               2816,2944,3072,3200,3328,3456,3584,3712,3840,3968,
                               0,128,256,384,512,640,768,896, 0,128, 0};

__device__ __constant__ float c_sizes[4][3] = {
    {32.f,40.f,50.f},{64.f,80.f,101.f},{128.f,161.f,203.f},{256.f,322.f,406.f}};
__device__ __constant__ float c_ratios[3] = {0.5f,1.0f,2.0f};
__device__ __constant__ int   c_str[4] = {8,16,32,64};

#define OFF_CLS_TW 0
#define OFF_REG_TW 2359296
#define OFF_CLS_OW 4718592
#define OFF_REG_OW 6488064

// -------- scratch --------
__device__ __align__(16) float g_b0[2*BATCH*256*5440];
__device__ __align__(16) float g_b1[2*BATCH*256*5440];
__device__ __align__(16) float g_cls[BATCH*CLS_C*5440];
__device__ __align__(16) float g_reg[BATCH*REG_C*5440];
__device__ __align__(16) float g_wt[6782976];
__device__ unsigned g_hist[16*65536];
__device__ unsigned g_thr[16];
__device__ int      g_cnt[16];
__device__ unsigned long long g_cand[(size_t)16*CAPB];
__device__ unsigned long long g_sel[16*DPI];
__device__ float g_cbox[BATCH*400*4];
__device__ float g_cscore[BATCH*400];
__device__ int   g_clab[BATCH*400];

__device__ __forceinline__ unsigned fkey(float f){
    unsigned b=__float_as_uint(f);
    return b ^ ((b>>31) ? 0xFFFFFFFFu : 0x80000000u);
}
__device__ __forceinline__ float unfkey(unsigned u){
    unsigned b=u ^ ((u>>31) ? 0x80000000u : 0xFFFFFFFFu);
    return __uint_as_float(b);
}

// -------- weight transform --------
__global__ void wtrans_k(const float* __restrict__ src, float* __restrict__ dst,
                         int Cout, int CoPad, int nL){
    size_t total=(size_t)nL*9*256*CoPad;
    for(size_t e=(size_t)blockIdx.x*blockDim.x+threadIdx.x; e<total;
        e+=(size_t)gridDim.x*blockDim.x){
        int co=(int)(e%CoPad); size_t t=e/CoPad;
        int ci=(int)(t%256); t/=256;
        int kpos=(int)(t%9); int layer=(int)(t/9);
        float v=0.f;
        if(co<Cout) v=src[(((size_t)layer*Cout+co)*256+ci)*9+kpos];
        dst[e]=v;
    }
}

// -------- conv core: 3x3 SAME, Cin=256, halo-tiled X, packed f32x2 FMA inner
__device__ __forceinline__ void conv_core(
    const float* __restrict__ Xb, int xStride,
    const float* __restrict__ Wt, int CoPad, int Cout,
    const float* __restrict__ bias,
    float* __restrict__ Yb, int yStride,
    int W, int H, int HW, int lw, int pixBase, int coBase, int relu,
    float* Ws, float* Xs){
    const int tid=threadIdx.x;
    const int tx=tid&15, ty=tid>>4;
    int validPx = HW - pixBase; if(validPx>128) validPx=128;
    const int SRS = W+4;
    const int hR = (validPx>>lw)+2;
    const int ES = hR*SRS;
    const int pixRow0 = pixBase>>lw;

    int goff0=0,goff1=0; bool v0=false,v1=false;
    const int e0=tid, e1=tid+256;
    if(e0<ES){int hr=e0/SRS;int c=e0-hr*SRS;int gr=pixRow0-1+hr;int gc=c-1;
        v0=(gr>=0&&gr<H&&gc>=0&&gc<W); goff0=gr*W+gc;}
    if(e1<ES){int hr=e1/SRS;int c=e1-hr*SRS;int gr=pixRow0-1+hr;int gc=c-1;
        v1=(gr>=0&&gr<H&&gc>=0&&gc<W); goff1=gr*W+gc;}

    const int px0=tx<<3;
    const bool pvalid = px0<validPx;
    const int prow = pvalid ? (px0>>lw) : 0;
    const int pcol = px0&(W-1);

    // acc2[i2][j]: packed pair over co = (ty*8+2*i2, ty*8+2*i2+1), pixel j
    unsigned long long acc2[4][8];
#pragma unroll
    for(int i=0;i<4;i++)
#pragma unroll
        for(int j=0;j<8;j++) acc2[i][j]=0ULL;

    for(int c0=0;c0<256;c0+=8){
#pragma unroll
        for(int i=0;i<9;i++){
            int q=tid*4+i*1024;
            int kpos=q>>10, ciL=(q>>7)&7, co=q&127;
            *(float4*)&Ws[q] =
                *(const float4*)&Wt[((size_t)(kpos*256+c0+ciL))*CoPad + coBase+co];
        }
#pragma unroll
        for(int ciL=0;ciL<8;ciL++){
            const float* xr=Xb+(size_t)(c0+ciL)*xStride;
            if(e0<ES) Xs[ciL*272+e0]= v0? xr[goff0]:0.f;
            if(e1<ES) Xs[ciL*272+e1]= v1? xr[goff1]:0.f;
        }
        __syncthreads();
#pragma unroll
        for(int k=0;k<8;k++){
            const int xbse=k*272;
#pragma unroll
            for(int kh=0;kh<3;kh++){
                const int rb=xbse+(prow+kh)*SRS+pcol;
                float xr[10];
                float4 u=*(const float4*)&Xs[rb];
                float4 v=*(const float4*)&Xs[rb+4];
                xr[0]=u.x;xr[1]=u.y;xr[2]=u.z;xr[3]=u.w;
                xr[4]=v.x;xr[5]=v.y;xr[6]=v.z;xr[7]=v.w;
                xr[8]=Xs[rb+8]; xr[9]=Xs[rb+9];
                // broadcast-pack x values once per row
                unsigned long long xb2[10];
#pragma unroll
                for(int t=0;t<10;t++){
                    unsigned xu=__float_as_uint(xr[t]);
                    asm("mov.b64 %0,{%1,%1};" : "=l"(xb2[t]) : "r"(xu));
                }
#pragma unroll
                for(int kw=0;kw<3;kw++){
                    // co-pairs straight from smem as 64-bit loads
                    const unsigned long long* w64=
                        (const unsigned long long*)&Ws[((kh*3+kw)*8+k)*128+(ty<<3)];
                    unsigned long long a2[4];
                    a2[0]=w64[0]; a2[1]=w64[1]; a2[2]=w64[2]; a2[3]=w64[3];
#pragma unroll
                    for(int i=0;i<4;i++)
#pragma unroll
                        for(int j=0;j<8;j++)
                            asm("fma.rn.f32x2 %0, %1, %2, %0;"
                                : "+l"(acc2[i][j]) : "l"(a2[i]), "l"(xb2[kw+j]));
                }
            }
        }
        __syncthreads();
    }
    if(pvalid){
#pragma unroll
        for(int i2=0;i2<4;i2++){
            int coE=coBase+(ty<<3)+2*i2;
#pragma unroll
            for(int half=0;half<2;half++){
                int co=coE+half;
                if(co<Cout){
                    float bv=bias[co];
                    float* yr=Yb+(size_t)co*yStride + pixBase+px0;
#pragma unroll
                    for(int j=0;j<8;j++){
                        unsigned lo,hi;
                        asm("mov.b64 {%0,%1},%2;" : "=r"(lo),"=r"(hi) : "l"(acc2[i2][j]));
                        float vv=__uint_as_float(half?hi:lo)+bv;
                        if(relu) vv=fmaxf(vv,0.f);
                        yr[j]=vv;
                    }
                }
            }
        }
    }
}

// -------- tower layer: all levels + both towers fused
__global__ __launch_bounds__(256,2)
void conv_tower_k(const float* __restrict__ xin,
                  const float* __restrict__ f0,const float* __restrict__ f1,
                  const float* __restrict__ f2,const float* __restrict__ f3,
                  const float* __restrict__ wtC,const float* __restrict__ wtR,
                  const float* __restrict__ bC,const float* __restrict__ bR,
                  float* __restrict__ out,int first){
    __shared__ float Ws[9216];
    __shared__ float Xs[8*272];
    const int bx=blockIdx.x;
    const int lvl=cb_lvl[bx], pixBase=cb_pix[bx];
    const int tower=blockIdx.y>>1, coBase=(blockIdx.y&1)<<7;
    const int b=blockIdx.z;
    const int W=cb_W[lvl],HW=cb_HW[lvl],lw=cb_LW[lvl],cum=cb_CUM[lvl];
    const float* Xb; int xs;
    if(first){
        const float* fl = (lvl==0)?f0:(lvl==1)?f1:(lvl==2)?f2:f3;
        Xb = fl + (size_t)b*256*HW; xs=HW;
    }else{
        Xb = xin + ((size_t)(tower*4+b)*256)*5440 + cum; xs=5440;
    }
    float* Yb = out + ((size_t)(tower*4+b)*256)*5440 + cum;
    conv_core(Xb,xs, tower?wtR:wtC, 256,256, tower?bR:bC,
              Yb,5440, W,W,HW,lw,pixBase,coBase,1, Ws,Xs);
}

// -------- heads: y<6 cls (720ch), y==6 reg (36ch)
__global__ __launch_bounds__(256,2)
void conv_head_k(const float* __restrict__ xin,
                 const float* __restrict__ wtCO,const float* __restrict__ wtRO,
                 const float* __restrict__ cob,const float* __restrict__ rob,
                 float* __restrict__ clsOut,float* __restrict__ regOut){
    __shared__ float Ws[9216];
    __shared__ float Xs[8*272];
    const int bx=blockIdx.x;
    const int lvl=cb_lvl[bx], pixBase=cb_pix[bx];
    const int y=blockIdx.y, b=blockIdx.z;
    const int W=cb_W[lvl],HW=cb_HW[lvl],lw=cb_LW[lvl],cum=cb_CUM[lvl];
    if(y<6){
        const float* Xb = xin + ((size_t)b*256)*5440 + cum;
        float* Yb = clsOut + (size_t)CLS_C*4*cum + (size_t)b*CLS_C*HW;
        conv_core(Xb,5440, wtCO,768,720, cob, Yb,HW,
                  W,W,HW,lw,pixBase,y*128,0, Ws,Xs);
    }else{
        const float* Xb = xin + ((size_t)(4+b)*256)*5440 + cum;
        float* Yb = regOut + (size_t)REG_C*4*cum + (size_t)b*REG_C*HW;
        conv_core(Xb,5440, wtRO,128,36, rob, Yb,HW,
                  W,W,HW,lw,pixBase,0,0, Ws,Xs);
    }
}

// -------- selection --------
__device__ __forceinline__ float sigm(float v){ return 1.0f/(1.0f+expf(-v)); }
__device__ __forceinline__ bool is_cand(float v){
    if(v>-2.93f) return true;
    if(v<=-2.96f) return false;
    return sigm(v)>0.05f;
}

__global__ void zero_k(){
    int i=blockIdx.x*blockDim.x+threadIdx.x;
    if(i<16*65536) g_hist[i]=0;
    if(i<16) g_cnt[i]=0;
}

__global__ void hist_k(const float* __restrict__ cls){
    const int g=blockIdx.y, b=g>>2, lvl=g&3;
    const int HW=cb_HW[lvl], n=CLS_C*HW;
    const float* p=cls + (size_t)CLS_C*4*cb_CUM[lvl] + (size_t)b*n;
    for(int m=blockIdx.x*blockDim.x+threadIdx.x;m<n;m+=gridDim.x*blockDim.x){
        float v=p[m];
        if(is_cand(v)) atomicAdd(&g_hist[g*65536+(fkey(sigm(v))>>16)],1u);
    }
}

__global__ void scan_k(){
    const int g=blockIdx.x;
    __shared__ unsigned seg[256];
    const unsigned* h=&g_hist[g*65536];
    unsigned s=0; int base=threadIdx.x*256;
    for(int k=0;k<256;k++) s+=h[65535-(base+k)];
    seg[threadIdx.x]=s;
    __syncthreads();
    if(threadIdx.x==0){
        unsigned cum=0,thr=0;
        for(int sg=0;sg<256;sg++){
            if(cum+seg[sg]>=DPI){
                for(int k=0;k<256;k++){
                    cum+=h[65535-(sg*256+k)];
                    if(cum>=DPI){thr=65535-(sg*256+k);break;}
                }
                break;
            }
            cum+=seg[sg];
        }
        g_thr[g]=thr;
    }
}

__global__ void collect_k(const float* __restrict__ cls){
    const int g=blockIdx.y, b=g>>2, lvl=g&3;
    const int HW=cb_HW[lvl], n=CLS_C*HW;
    const unsigned thr=g_thr[g];
    const float* p=cls + (size_t)CLS_C*4*cb_CUM[lvl] + (size_t)b*n;
    for(int m=blockIdx.x*blockDim.x+threadIdx.x;m<n;m+=gridDim.x*blockDim.x){
        float v=p[m];
        if(!is_cand(v)) continue;
        unsigned u=fkey(sigm(v));
        if((u>>16)>=thr){
            int pos=atomicAdd(&g_cnt[g],1);
            if(pos<CAPB){
                int co=m/HW, pix=m-co*HW;
                unsigned nn=(unsigned)(pix*CLS_C+co);
                g_cand[(size_t)g*CAPB+pos]=((unsigned long long)u<<32)|(0xFFFFFFFFu-nn);
            }
        }
    }
}

__global__ __launch_bounds__(256)
void select_k(){
    const int g=blockIdx.x;
    int cnt=g_cnt[g]; if(cnt>CAPB) cnt=CAPB;
    unsigned long long* cand=&g_cand[(size_t)g*CAPB];
    __shared__ unsigned long long sc[4096];
    __shared__ unsigned long long wmax[8];
    __shared__ int wpos[8];
    const int tid=threadIdx.x, lane=tid&31, wid=tid>>5;
    const bool cached = cnt<=4096;
    if(cached) for(int i=tid;i<cnt;i+=256) sc[i]=cand[i];
    __syncthreads();
    unsigned long long* src = cached? sc : cand;
    for(int r=0;r<DPI;r++){
        unsigned long long mk=0ULL; int mp=-1;
        for(int i=tid;i<cnt;i+=256){
            unsigned long long k=src[i];
            if(k>mk){mk=k;mp=i;}
        }
#pragma unroll
        for(int off=16;off>0;off>>=1){
            unsigned long long ok=__shfl_down_sync(0xFFFFFFFFu,mk,off);
            int op=__shfl_down_sync(0xFFFFFFFFu,mp,off);
            if(ok>mk){mk=ok;mp=op;}
        }
        if(lane==0){wmax[wid]=mk;wpos[wid]=mp;}
        __syncthreads();
        if(tid==0){
            unsigned long long bk=wmax[0]; int bp=wpos[0];
#pragma unroll
            for(int w=1;w<8;w++) if(wmax[w]>bk){bk=wmax[w];bp=wpos[w];}
            g_sel[g*DPI+r]=bk;
            if(bp>=0) src[bp]=0ULL;
        }
        __syncthreads();
    }
}

__global__ void decode_k(const float* __restrict__ reg,
                         const int* __restrict__ ph,const int* __restrict__ pw){
    const int g=blockIdx.x, b=g>>2, lvl=g&3;
    const int r=threadIdx.x;
    if(r>=DPI) return;
    const int W=cb_W[lvl], HW=cb_HW[lvl];
    const float ih=(float)(*ph), iw=(float)(*pw);
    const int slot=b*400+lvl*DPI+r;
    unsigned long long k=g_sel[g*DPI+r];
    float* bx=&g_cbox[(size_t)slot*4];
    if(!k){ g_cscore[slot]=-1.f; g_clab[slot]=-1; bx[0]=bx[1]=bx[2]=bx[3]=0.f; return; }
    float sc=unfkey((unsigned)(k>>32));
    unsigned n=0xFFFFFFFFu-(unsigned)(k&0xFFFFFFFFu);
    int pix=(int)(n/CLS_C); int co=(int)(n-(unsigned)pix*CLS_C);
    int a=co/NC, c=co-a*NC;
    int hh=pix/W, ww=pix-hh*W;
    float size=c_sizes[lvl][a%3];
    float hr=sqrtf(c_ratios[a/3]);
    float wr=1.f/hr;
    float ws=wr*size, hs=hr*size;
    float st=(float)c_str[lvl];
    float sx=(float)ww*st, sy=(float)hh*st;
    float ax1=fminf(fmaxf(sx+rintf(-ws*0.5f),0.f),iw);
    float ay1=fminf(fmaxf(sy+rintf(-hs*0.5f),0.f),ih);
    float ax2=fminf(fmaxf(sx+rintf( ws*0.5f),0.f),iw);
    float ay2=fminf(fmaxf(sy+rintf( hs*0.5f),0.f),ih);
    float aw=ax2-ax1, ah=ay2-ay1;
    float cx=ax1+0.5f*aw, cy=ay1+0.5f*ah;
    const float* R=reg + (size_t)REG_C*4*cb_CUM[lvl] + (size_t)b*REG_C*HW;
    float dx=R[(a*4+0)*HW+pix];
    float dy=R[(a*4+1)*HW+pix];
    const float CLIPV=(float)4.135166556742356;
    float dw=fminf(R[(a*4+2)*HW+pix],CLIPV);
    float dh=fminf(R[(a*4+3)*HW+pix],CLIPV);
    float pcx=dx*aw+cx, pcy=dy*ah+cy;
    float pw_=expf(dw)*aw, ph_=expf(dh)*ah;
    bx[0]=fminf(fmaxf(pcx-0.5f*pw_,0.f),iw);
    bx[1]=fminf(fmaxf(pcy-0.5f*ph_,0.f),ih);
    bx[2]=fminf(fmaxf(pcx+0.5f*pw_,0.f),iw);
    bx[3]=fminf(fmaxf(pcy+0.5f*ph_,0.f),ih);
    g_cscore[slot]=sc;
    g_clab[slot]=c;
}

__global__ __launch_bounds__(512)
void final_k(float* __restrict__ out,const int* __restrict__ ph,const int* __restrict__ pw){
    int b=blockIdx.x, tid=threadIdx.x;
    __shared__ unsigned long long key[512];
    __shared__ float X1[512],Y1[512],X2[512],Y2[512],AR[512],SC[512];
    __shared__ float BX1[512],BY1[512],BX2[512],BY2[512];
    __shared__ int LB[512];
    __shared__ unsigned char KP[512];
    float ih=(float)(*ph), iw=(float)(*pw);
    float ob=fmaxf(ih,iw)+1.f;
    if(tid<400)
        key[tid]=((unsigned long long)fkey(g_cscore[b*400+tid])<<32)|(0xFFFFFFFFu-(unsigned)tid);
    else key[tid]=0ULL;
    __syncthreads();
    for(int k=2;k<=512;k<<=1)
        for(int j=k>>1;j>0;j>>=1){
            int ix=tid^j;
            if(ix>tid){
                unsigned long long a=key[tid],c=key[ix];
                if((a>c)==((tid&k)==0)){key[tid]=c;key[ix]=a;}
            }
            __syncthreads();
        }
    {
        unsigned long long k=key[511-tid];
        float sc=-1.f; int lb=-1; float b0=0,b1=0,b2=0,b3=0;
        if(k){
            unsigned i=0xFFFFFFFFu-(unsigned)(k&0xFFFFFFFFu);
            sc=unfkey((unsigned)(k>>32));
            lb=g_clab[b*400+i];
            const float* bp=&g_cbox[((size_t)b*400+i)*4];
            b0=bp[0];b1=bp[1];b2=bp[2];b3=bp[3];
        }
        float o=(float)lb*ob;
        BX1[tid]=b0;BY1[tid]=b1;BX2[tid]=b2;BY2[tid]=b3;
        X1[tid]=b0+o;Y1[tid]=b1+o;X2[tid]=b2+o;Y2[tid]=b3+o;
        SC[tid]=sc;LB[tid]=lb;
        AR[tid]=(X2[tid]-X1[tid])*(Y2[tid]-Y1[tid]);
        KP[tid]=(sc>0.05f)?1:0;
    }
    __syncthreads();
    for(int i=0;i<400;i++){
        if(KP[i]&&tid>i&&tid<400&&KP[tid]){
            float w=fmaxf(fminf(X2[i],X2[tid])-fmaxf(X1[i],X1[tid]),0.f);
            float h=fmaxf(fminf(Y2[i],Y2[tid])-fmaxf(Y1[i],Y1[tid]),0.f);
            float it=w*h;
            float iou=it/(AR[i]+AR[tid]-it+1e-9f);
            if(iou>0.5f) KP[tid]=0;
        }
        __syncthreads();
    }
    if(tid==0){
        int o=0;
        for(int r=0;r<400&&o<DPI;r++) if(KP[r]){
            out[(b*DPI+o)*4+0]=BX1[r]; out[(b*DPI+o)*4+1]=BY1[r];
            out[(b*DPI+o)*4+2]=BX2[r]; out[(b*DPI+o)*4+3]=BY2[r];
            out[1600+b*DPI+o]=SC[r];   out[2000+b*DPI+o]=(float)LB[r];
            o++;
        }
        for(;o<DPI;o++){
            out[(b*DPI+o)*4+0]=0.f; out[(b*DPI+o)*4+1]=0.f;
            out[(b*DPI+o)*4+2]=0.f; out[(b*DPI+o)*4+3]=0.f;
            out[1600+b*DPI+o]=0.f;  out[2000+b*DPI+o]=-1.f;
        }
    }
}

extern "C" void kernel_launch(void* const* d_in, const int* in_sizes, int n_in,
                              void* d_out, int out_size){
    const float* f0=(const float*)d_in[0];
    const float* f1=(const float*)d_in[1];
    const float* f2=(const float*)d_in[2];
    const float* f3=(const float*)d_in[3];
    const float* ctw=(const float*)d_in[4];
    const float* ctb=(const float*)d_in[5];
    const float* cow=(const float*)d_in[6];
    const float* cob=(const float*)d_in[7];
    const float* rtw=(const float*)d_in[8];
    const float* rtb=(const float*)d_in[9];
    const float* row_=(const float*)d_in[10];
    const float* rob=(const float*)d_in[11];
    const int* ph=(const int*)d_in[12];
    const int* pw=(const int*)d_in[13];

    float *b0,*b1,*cls,*reg,*wt;
    cudaGetSymbolAddress((void**)&b0,g_b0);
    cudaGetSymbolAddress((void**)&b1,g_b1);
    cudaGetSymbolAddress((void**)&cls,g_cls);
    cudaGetSymbolAddress((void**)&reg,g_reg);
    cudaGetSymbolAddress((void**)&wt,g_wt);

    wtrans_k<<<2048,256>>>(ctw,wt+OFF_CLS_TW,256,256,4);
    wtrans_k<<<2048,256>>>(rtw,wt+OFF_REG_TW,256,256,4);
    wtrans_k<<<2048,256>>>(cow,wt+OFF_CLS_OW,720,768,1);
    wtrans_k<<<1024,256>>>(row_,wt+OFF_REG_OW,36,128,1);

    const float* wtC=wt+OFF_CLS_TW;
    const float* wtR=wt+OFF_REG_TW;

    conv_tower_k<<<dim3(43,4,BATCH),256>>>(b1,f0,f1,f2,f3,
        wtC+0*589824,wtR+0*589824,ctb+0,  rtb+0,  b0,1);
    conv_tower_k<<<dim3(43,4,BATCH),256>>>(b0,f0,f1,f2,f3,
        wtC+1*589824,wtR+1*589824,ctb+256,rtb+256,b1,0);
    conv_tower_k<<<dim3(43,4,BATCH),256>>>(b1,f0,f1,f2,f3,
        wtC+2*589824,wtR+2*589824,ctb+512,rtb+512,b0,0);
    conv_tower_k<<<dim3(43,4,BATCH),256>>>(b0,f0,f1,f2,f3,
        wtC+3*589824,wtR+3*589824,ctb+768,rtb+768,b1,0);
    conv_head_k<<<dim3(43,7,BATCH),256>>>(b1,wt+OFF_CLS_OW,wt+OFF_REG_OW,
        cob,rob,cls,reg);

    zero_k<<<4096,256>>>();
    hist_k<<<dim3(256,16),256>>>(cls);
    scan_k<<<16,256>>>();
    collect_k<<<dim3(256,16),256>>>(cls);
    select_k<<<16,256>>>();
    decode_k<<<16,128>>>(reg,ph,pw);
    final_k<<<BATCH,512>>>((float*)d_out,ph,pw);
}